// round 4
// baseline (speedup 1.0000x reference)
#include <cuda_runtime.h>
#include <cstdint>

// Problem shapes
#define Bq 8
#define Sq 8192
#define Nq 16
#define Dq 64
#define Mq 64
#define NCHUNK 8
#define SSUB (Sq / NCHUNK)   // 1024 s-steps per block
#define TILE 16              // s-rows staged per sync
#define NIT (SSUB / TILE)    // 64 iterations

#define V_ELEMS   (Bq * Nq * Mq)            // 8192
#define SST_ELEMS (Bq * Nq * Mq * Dq)       // 524288

// Scratch for deterministic two-phase reduction
__device__ float g_sst_part[Bq * Nq * NCHUNK * Mq * Dq];  // ~16.8 MB
__device__ float g_z_part[Bq * Nq * NCHUNK * Dq];

__device__ __forceinline__ float elu1(float x) {
    return x > 0.0f ? x + 1.0f : __expf(x);
}
__device__ __forceinline__ uint64_t fma2(uint64_t a, uint64_t b, uint64_t c) {
    uint64_t d;
    asm("fma.rn.f32x2 %0, %1, %2, %3;" : "=l"(d) : "l"(a), "l"(b), "l"(c));
    return d;
}
__device__ __forceinline__ uint64_t add2(uint64_t a, uint64_t b) {
    uint64_t d;
    asm("add.rn.f32x2 %0, %1, %2;" : "=l"(d) : "l"(a), "l"(b));
    return d;
}

struct SMem {
    float ks[2][TILE][Dq];        // 8 KB  (elu'd, masked K)
    float vd[2][TILE][2 * Mq];    // 16 KB (V duplicated: vd[2m]=vd[2m+1]=v[m])
};
// final cross-sgroup reduction reuses this storage (needs 16 KB <= 24 KB)

// ---------------------------------------------------------------------------
// Phase 1: per-chunk partial Sst[bn] (64x64) and Z[bn] (64).
// 256 threads = 2 s-groups x 128; each thread owns a 4(m) x 8(d) tile
// as 16 f32x2 accumulators. Inner loop: 4 LDS.128 + 16 FFMA2 per s-row.
// ---------------------------------------------------------------------------
__global__ void __launch_bounds__(256) rcla_phase1(
    const float* __restrict__ key,     // [B,S,N,D]
    const float* __restrict__ value,   // [B,S,N,M]
    const int* __restrict__ key_mask)  // [B,S], nonzero = masked
{
    __shared__ SMem sm;

    const int bn = blockIdx.x;     // 0..127
    const int c  = blockIdx.y;     // 0..7
    const int b  = bn >> 4;
    const int n  = bn & 15;
    const int tid = threadIdx.x;

    // ---- loader mapping: 16 rows x 16 threads; each thread loads 1 K-float4
    //      and 1 V-float4 per iteration ----
    const int lrow = tid >> 4;           // 0..15
    const int loff = (tid & 15) << 2;    // 0,4,...,60
    const int s0 = c * SSUB + lrow;
    const float* kptr = key   + (((size_t)b * Sq + s0) * Nq + n) * Dq + loff;
    const float* vptr = value + (((size_t)b * Sq + s0) * Nq + n) * Mq + loff;
    const int*   mptr = key_mask + b * Sq + s0;
    const size_t KSTR = (size_t)TILE * Nq * Dq;   // floats per iteration
    const size_t VSTR = (size_t)TILE * Nq * Mq;

    // ---- compute mapping ----
    const int sg = tid >> 7;             // 0/1: which half of the 16 rows
    const int t  = tid & 127;
    const int m0 = ((t >> 3) & 15) << 2; // 0,4,...,60
    const int d0 = (t & 7) << 3;         // 0,8,...,56

    uint64_t acc[4][4];                  // [mi][d-pair j]: (d0+2j, d0+2j+1)
#pragma unroll
    for (int i = 0; i < 4; i++)
#pragma unroll
        for (int j = 0; j < 4; j++) acc[i][j] = 0ull;
    float zacc = 0.0f;

    // prefetch iteration 0
    float4 kin = *(const float4*)kptr;
    float4 vin = *(const float4*)vptr;
    int    min_ = *mptr;

    for (int it = 0; it < NIT; it++) {
        const int buf = it & 1;

        // transform + stage current tile
        {
            const float mm = min_ ? 0.0f : 1.0f;
            float4 r;
            r.x = mm * elu1(kin.x);
            r.y = mm * elu1(kin.y);
            r.z = mm * elu1(kin.z);
            r.w = mm * elu1(kin.w);
            *(float4*)&sm.ks[buf][lrow][loff] = r;
            float4 va = make_float4(vin.x, vin.x, vin.y, vin.y);
            float4 vb = make_float4(vin.z, vin.z, vin.w, vin.w);
            *(float4*)&sm.vd[buf][lrow][2 * loff]     = va;
            *(float4*)&sm.vd[buf][lrow][2 * loff + 4] = vb;
        }

        // prefetch next tile (latency hidden behind this iteration's compute)
        kptr += KSTR; vptr += VSTR; mptr += TILE;
        if (it + 1 < NIT) {
            kin  = *(const float4*)kptr;
            vin  = *(const float4*)vptr;
            min_ = *mptr;
        }

        __syncthreads();   // staged tile visible; prev reads of this buf done

        // compute 8 rows of this half
#pragma unroll
        for (int r = 0; r < TILE / 2; r++) {
            const int row = (sg << 3) + r;
            const ulonglong2 kA = *(const ulonglong2*)&sm.ks[buf][row][d0];
            const ulonglong2 kB = *(const ulonglong2*)&sm.ks[buf][row][d0 + 4];
            const ulonglong2 vA = *(const ulonglong2*)&sm.vd[buf][row][2 * m0];
            const ulonglong2 vB = *(const ulonglong2*)&sm.vd[buf][row][2 * m0 + 4];
            acc[0][0] = fma2(vA.x, kA.x, acc[0][0]);
            acc[0][1] = fma2(vA.x, kA.y, acc[0][1]);
            acc[0][2] = fma2(vA.x, kB.x, acc[0][2]);
            acc[0][3] = fma2(vA.x, kB.y, acc[0][3]);
            acc[1][0] = fma2(vA.y, kA.x, acc[1][0]);
            acc[1][1] = fma2(vA.y, kA.y, acc[1][1]);
            acc[1][2] = fma2(vA.y, kB.x, acc[1][2]);
            acc[1][3] = fma2(vA.y, kB.y, acc[1][3]);
            acc[2][0] = fma2(vB.x, kA.x, acc[2][0]);
            acc[2][1] = fma2(vB.x, kA.y, acc[2][1]);
            acc[2][2] = fma2(vB.x, kB.x, acc[2][2]);
            acc[2][3] = fma2(vB.x, kB.y, acc[2][3]);
            acc[3][0] = fma2(vB.y, kA.x, acc[3][0]);
            acc[3][1] = fma2(vB.y, kA.y, acc[3][1]);
            acc[3][2] = fma2(vB.y, kB.x, acc[3][2]);
            acc[3][3] = fma2(vB.y, kB.y, acc[3][3]);
        }

        // Z column sums (64 threads cover all 16 rows)
        if (tid < Dq) {
#pragma unroll
            for (int r = 0; r < TILE; r++) zacc += sm.ks[buf][r][tid];
        }
    }

    // ---- cross-sgroup reduction in smem, then write partials ----
    __syncthreads();
    uint64_t* scratch = (uint64_t*)&sm;   // 128 threads x 16 u64 = 16 KB
    if (sg == 1) {
#pragma unroll
        for (int i = 0; i < 4; i++)
#pragma unroll
            for (int j = 0; j < 4; j++)
                scratch[t * 16 + i * 4 + j] = acc[i][j];
    }
    __syncthreads();
    if (sg == 0) {
        float* outs = g_sst_part + ((size_t)bn * NCHUNK + c) * (Mq * Dq);
#pragma unroll
        for (int i = 0; i < 4; i++) {
#pragma unroll
            for (int j = 0; j < 4; j++)
                acc[i][j] = add2(acc[i][j], scratch[t * 16 + i * 4 + j]);
            ulonglong2 lo, hi;
            lo.x = acc[i][0]; lo.y = acc[i][1];
            hi.x = acc[i][2]; hi.y = acc[i][3];
            *(ulonglong2*)&outs[(m0 + i) * Dq + d0]     = lo;
            *(ulonglong2*)&outs[(m0 + i) * Dq + d0 + 4] = hi;
        }
    }
    if (tid < Dq) {
        g_z_part[((size_t)bn * NCHUNK + c) * Dq + tid] = zacc;
    }
}

// ---------------------------------------------------------------------------
// Phase 2: deterministic chunk reduction + V epilogue. One block per (b,n).
// ---------------------------------------------------------------------------
__global__ void __launch_bounds__(256) rcla_phase2(
    const float* __restrict__ query,  // [B,N,D]
    float* __restrict__ outV,         // [B,N,M]
    float* __restrict__ outS,         // [B,N,M,D]
    float* __restrict__ outZ)         // [B,N,D]
{
    const int bn = blockIdx.x;
    const int tid = threadIdx.x;

    __shared__ float sst[Mq * Dq];
    __shared__ float qs[Dq];
    __shared__ float prod[Dq];
    __shared__ float sinv;

    const float* base = g_sst_part + (size_t)bn * NCHUNK * (Mq * Dq);
    for (int e = tid; e < Mq * Dq; e += 256) {
        float sum = 0.0f;
#pragma unroll
        for (int c = 0; c < NCHUNK; c++) sum += base[c * (Mq * Dq) + e];
        sst[e] = sum;
        outS[(size_t)bn * (Mq * Dq) + e] = sum;
    }
    if (tid < Dq) {
        float zs = 0.0f;
#pragma unroll
        for (int c = 0; c < NCHUNK; c++)
            zs += g_z_part[((size_t)bn * NCHUNK + c) * Dq + tid];
        outZ[bn * Dq + tid] = zs;
        const float q = elu1(query[bn * Dq + tid]);
        qs[tid] = q;
        prod[tid] = q * zs;
    }
    __syncthreads();
    if (tid == 0) {
        float s = 0.0f;
#pragma unroll
        for (int d = 0; d < Dq; d++) s += prod[d];
        sinv = 1.0f / (s + 1e-6f);
    }
    __syncthreads();
    if (tid < Mq) {
        float v = 0.0f;
#pragma unroll
        for (int d = 0; d < Dq; d++) v += qs[d] * sst[tid * Dq + d];
        outV[bn * Mq + tid] = v * sinv;
    }
}

// ---------------------------------------------------------------------------
extern "C" void kernel_launch(void* const* d_in, const int* in_sizes, int n_in,
                              void* d_out, int out_size)
{
    const float* query = (const float*)d_in[0];
    const float* key   = (const float*)d_in[1];
    const float* value = (const float*)d_in[2];
    const int*   mask  = (const int*)d_in[3];

    float* out  = (float*)d_out;
    float* outV = out;                        // [B,N,M]
    float* outS = out + V_ELEMS;              // [B,N,M,D]
    float* outZ = out + V_ELEMS + SST_ELEMS;  // [B,N,D]

    rcla_phase1<<<dim3(Bq * Nq, NCHUNK), 256>>>(key, value, mask);
    rcla_phase2<<<Bq * Nq, 256>>>(query, outV, outS, outZ);
}

// round 7
// speedup vs baseline: 1.7805x; 1.7805x over previous
#include <cuda_runtime.h>
#include <cstdint>

// Shapes
#define Bq 8
#define Sq 8192
#define Nq 16
#define ST 32                     // s-rows per tile
#define NT (Sq / ST)              // 256 tiles
#define RSTRIDE 272               // smem row stride bytes (136 bf16)
#define TILE_B (ST * RSTRIDE)     // 8704
#define BUF_B (2 * TILE_B)        // 17408 = V tile + K tile
#define V_ELEMS 8192
#define SST_ELEMS 524288

static __device__ __forceinline__ float elu1(float x) {
    return x > 0.0f ? x + 1.0f : __expf(x);
}
static __device__ __forceinline__ uint32_t smem_u32(const void* p) {
    uint32_t a;
    asm("{ .reg .u64 t; cvta.to.shared.u64 t, %1; cvt.u32.u64 %0, t; }" : "=r"(a) : "l"(p));
    return a;
}
static __device__ __forceinline__ uint32_t pk(float hi, float lo) {
    uint32_t r;
    asm("cvt.rn.bf16x2.f32 %0, %1, %2;" : "=r"(r) : "f"(hi), "f"(lo));
    return r;
}
static __device__ __forceinline__ float bf_lo(uint32_t p) {   // lower bf16 -> float
    return __uint_as_float(p << 16);
}
static __device__ __forceinline__ float bf_up(uint32_t p) {   // upper bf16 -> float
    return __uint_as_float(p & 0xFFFF0000u);
}
static __device__ __forceinline__ void ldsm4t(uint32_t* r, uint32_t a) {
    asm volatile("ldmatrix.sync.aligned.m8n8.x4.trans.shared.b16 {%0,%1,%2,%3}, [%4];"
                 : "=r"(r[0]), "=r"(r[1]), "=r"(r[2]), "=r"(r[3]) : "r"(a));
}
static __device__ __forceinline__ void mma16816(float* c, const uint32_t* a,
                                                uint32_t b0, uint32_t b1) {
    asm volatile(
        "mma.sync.aligned.m16n8k16.row.col.f32.bf16.bf16.f32 "
        "{%0,%1,%2,%3}, {%4,%5,%6,%7}, {%8,%9}, {%0,%1,%2,%3};"
        : "+f"(c[0]), "+f"(c[1]), "+f"(c[2]), "+f"(c[3])
        : "r"(a[0]), "r"(a[1]), "r"(a[2]), "r"(a[3]), "r"(b0), "r"(b1));
}
static __device__ __forceinline__ void sts128(uint32_t a, uint32_t x, uint32_t y,
                                              uint32_t z, uint32_t w) {
    asm volatile("st.shared.v4.b32 [%0], {%1,%2,%3,%4};"
                 :: "r"(a), "r"(x), "r"(y), "r"(z), "r"(w) : "memory");
}

// ---------------------------------------------------------------------------
__global__ void __launch_bounds__(256) rcla_hmma(
    const float* __restrict__ query,   // [B,N,64]
    const float* __restrict__ key,     // [B,S,N,64]
    const float* __restrict__ value,   // [B,S,N,64]
    const int*   __restrict__ kmask,   // [B,S] nonzero = masked
    float* __restrict__ outV,          // [B,N,64]
    float* __restrict__ outS,          // [B,N,64,64]
    float* __restrict__ outZ)          // [B,N,64]
{
    __shared__ __align__(16) unsigned char s_tiles[2 * BUF_B];  // 34816 B
    __shared__ float s_z[ST][64];                               // 8 KB
    __shared__ float s_q[64];
    __shared__ float s_red[64];
    __shared__ float s_v[2][64];
    __shared__ float s_sinv;

    const int tid = threadIdx.x;
    const int wid = tid >> 5;
    const int lid = tid & 31;
    const int bn = blockIdx.x;
    const int b = bn >> 4;
    const int n = bn & 15;

    const uint32_t sb = smem_u32(s_tiles);

    // ---- staging mapping: thread -> (s_loc, 8 consecutive d) ----
    const int s_loc = tid >> 3;            // 0..31
    const int dgrp = (tid & 7) * 8;        // 0,8,...,56
    const uint32_t st_off = (uint32_t)s_loc * RSTRIDE + dgrp * 2;   // 16B aligned

    const float* kg = key   + (((size_t)b * Sq + s_loc) * Nq + n) * 64 + dgrp;
    const float* vg = value + (((size_t)b * Sq + s_loc) * Nq + n) * 64 + dgrp;
    const int*   mg = kmask + b * Sq + s_loc;
    const size_t GSTR = (size_t)ST * Nq * 64;   // floats per tile

    // ---- mma mapping ----
    const int mbase = (wid >> 2) * 64;     // 0: V_hi rows, 64: V_lo rows
    const int dbase = (wid & 3) * 32;      // d' window
    const int g = lid >> 2;                // fragment row group
    const int tig = lid & 3;

    // ldmatrix per-lane byte offsets (within a tile)
    const uint32_t offA = (uint32_t)((lid & 7) + ((lid & 16) ? 8 : 0)) * RSTRIDE
                        + (uint32_t)(mbase + ((lid & 8) ? 8 : 0)) * 2;
    const uint32_t offB = (uint32_t)((lid & 7) + ((lid & 8) ? 8 : 0)) * RSTRIDE
                        + (uint32_t)(dbase + ((lid & 16) ? 8 : 0)) * 2;

    float c[4][4][4];
#pragma unroll
    for (int i = 0; i < 4; i++)
#pragma unroll
        for (int j = 0; j < 4; j++)
#pragma unroll
            for (int r = 0; r < 4; r++) c[i][j][r] = 0.0f;
    float zacc[8];
#pragma unroll
    for (int j = 0; j < 8; j++) zacc[j] = 0.0f;

    // prefetch tile 0
    float4 k0 = *(const float4*)kg;
    float4 k1 = *(const float4*)(kg + 4);
    float4 v0 = *(const float4*)vg;
    float4 v1 = *(const float4*)(vg + 4);
    int mk = *mg;

    for (int it = 0; it < NT; it++) {
        const int buf = it & 1;
        const uint32_t vt = sb + buf * BUF_B;            // V tile base
        const uint32_t kt = vt + TILE_B;                 // K tile base

        // ---- stage K (mask + elu + split) ----
        {
            const float mm = mk ? 0.0f : 1.0f;
            float f0 = mm * elu1(k0.x), f1 = mm * elu1(k0.y);
            float f2 = mm * elu1(k0.z), f3 = mm * elu1(k0.w);
            float f4 = mm * elu1(k1.x), f5 = mm * elu1(k1.y);
            float f6 = mm * elu1(k1.z), f7 = mm * elu1(k1.w);
            zacc[0] += f0; zacc[1] += f1; zacc[2] += f2; zacc[3] += f3;
            zacc[4] += f4; zacc[5] += f5; zacc[6] += f6; zacc[7] += f7;
            const uint32_t h01 = pk(f1, f0), h23 = pk(f3, f2);
            const uint32_t h45 = pk(f5, f4), h67 = pk(f7, f6);
            sts128(kt + st_off, h01, h23, h45, h67);
            const uint32_t l01 = pk(f1 - bf_up(h01), f0 - bf_lo(h01));
            const uint32_t l23 = pk(f3 - bf_up(h23), f2 - bf_lo(h23));
            const uint32_t l45 = pk(f5 - bf_up(h45), f4 - bf_lo(h45));
            const uint32_t l67 = pk(f7 - bf_up(h67), f6 - bf_lo(h67));
            sts128(kt + st_off + 128, l01, l23, l45, l67);   // cols d+64
        }
        // ---- stage V (split) ----
        {
            const float f0 = v0.x, f1 = v0.y, f2 = v0.z, f3 = v0.w;
            const float f4 = v1.x, f5 = v1.y, f6 = v1.z, f7 = v1.w;
            const uint32_t h01 = pk(f1, f0), h23 = pk(f3, f2);
            const uint32_t h45 = pk(f5, f4), h67 = pk(f7, f6);
            sts128(vt + st_off, h01, h23, h45, h67);
            const uint32_t l01 = pk(f1 - bf_up(h01), f0 - bf_lo(h01));
            const uint32_t l23 = pk(f3 - bf_up(h23), f2 - bf_lo(h23));
            const uint32_t l45 = pk(f5 - bf_up(h45), f4 - bf_lo(h45));
            const uint32_t l67 = pk(f7 - bf_up(h67), f6 - bf_lo(h67));
            sts128(vt + st_off + 128, l01, l23, l45, l67);
        }

        // ---- prefetch next tile (overlaps sync + mma) ----
        if (it + 1 < NT) {
            kg += GSTR; vg += GSTR; mg += ST;
            k0 = *(const float4*)kg;
            k1 = *(const float4*)(kg + 4);
            v0 = *(const float4*)vg;
            v1 = *(const float4*)(vg + 4);
            mk = *mg;
        }

        __syncthreads();

        // ---- compute: 2 k-steps of 16 ----
#pragma unroll
        for (int ks = 0; ks < 2; ks++) {
            const uint32_t rowoff = (uint32_t)ks * 16 * RSTRIDE;
            uint32_t a[4][4], bb[2][4];
#pragma unroll
            for (int ai = 0; ai < 4; ai++)
                ldsm4t(a[ai], vt + rowoff + offA + ai * 32);
#pragma unroll
            for (int bj = 0; bj < 2; bj++)
                ldsm4t(bb[bj], kt + rowoff + offB + bj * 32);
#pragma unroll
            for (int ai = 0; ai < 4; ai++)
#pragma unroll
                for (int nb = 0; nb < 4; nb++)
                    mma16816(c[ai][nb], a[ai],
                             bb[nb >> 1][(nb & 1) * 2],
                             bb[nb >> 1][(nb & 1) * 2 + 1]);
        }
        __syncthreads();   // all reads of buf done before restaging it
    }

    // ---- Z reduction, q, sinv ----
#pragma unroll
    for (int j = 0; j < 8; j++) s_z[s_loc][dgrp + j] = zacc[j];
    __syncthreads();
    if (tid < 64) {
        float z = 0.0f;
#pragma unroll
        for (int p = 0; p < ST; p++) z += s_z[p][tid];
        outZ[bn * 64 + tid] = z;
        const float q = elu1(query[bn * 64 + tid]);
        s_q[tid] = q;
        s_red[tid] = q * z;
    }
    __syncthreads();
    if (tid == 0) {
        float s = 0.0f;
#pragma unroll
        for (int d = 0; d < 64; d++) s += s_red[d];
        s_sinv = 1.0f / (s + 1e-6f);
    }
    __syncthreads();

    // ---- quadrant fold (tiles memory reused as fp32 buffer) ----
    float* fold = (float*)s_tiles;

    // stage 1: warps 4-7 (V_lo rows) publish their C
    if (wid >= 4) {
#pragma unroll
        for (int ai = 0; ai < 4; ai++)
#pragma unroll
            for (int nb = 0; nb < 4; nb++) {
                const int m = ai * 16 + g;                 // mbase-64 folded out
                const int d0 = dbase + nb * 8 + 2 * tig;
                fold[m * 130 + d0]       = c[ai][nb][0];
                fold[m * 130 + d0 + 1]   = c[ai][nb][1];
                fold[(m + 8) * 130 + d0]     = c[ai][nb][2];
                fold[(m + 8) * 130 + d0 + 1] = c[ai][nb][3];
            }
    }
    __syncthreads();
    if (wid < 4) {
#pragma unroll
        for (int ai = 0; ai < 4; ai++)
#pragma unroll
            for (int nb = 0; nb < 4; nb++) {
                const int m = ai * 16 + g;
                const int d0 = dbase + nb * 8 + 2 * tig;
                c[ai][nb][0] += fold[m * 130 + d0];
                c[ai][nb][1] += fold[m * 130 + d0 + 1];
                c[ai][nb][2] += fold[(m + 8) * 130 + d0];
                c[ai][nb][3] += fold[(m + 8) * 130 + d0 + 1];
            }
    }
    __syncthreads();
    // stage 2: warps 2,3 (K_lo cols) publish summed C at d'-64
    if (wid == 2 || wid == 3) {
#pragma unroll
        for (int ai = 0; ai < 4; ai++)
#pragma unroll
            for (int nb = 0; nb < 4; nb++) {
                const int m = ai * 16 + g;
                const int d0 = dbase - 64 + nb * 8 + 2 * tig;
                fold[m * 66 + d0]       = c[ai][nb][0];
                fold[m * 66 + d0 + 1]   = c[ai][nb][1];
                fold[(m + 8) * 66 + d0]     = c[ai][nb][2];
                fold[(m + 8) * 66 + d0 + 1] = c[ai][nb][3];
            }
    }
    __syncthreads();

    // ---- final: warps 0,1 hold Sst; write outS + V partials ----
    if (wid < 2) {
        float vr[4][2];
#pragma unroll
        for (int ai = 0; ai < 4; ai++) { vr[ai][0] = 0.0f; vr[ai][1] = 0.0f; }
        float* so = outS + (size_t)bn * 4096;
#pragma unroll
        for (int ai = 0; ai < 4; ai++)
#pragma unroll
            for (int nb = 0; nb < 4; nb++) {
                const int m = ai * 16 + g;
                const int d0 = dbase + nb * 8 + 2 * tig;
                float c0 = c[ai][nb][0] + fold[m * 66 + d0];
                float c1 = c[ai][nb][1] + fold[m * 66 + d0 + 1];
                float c2 = c[ai][nb][2] + fold[(m + 8) * 66 + d0];
                float c3 = c[ai][nb][3] + fold[(m + 8) * 66 + d0 + 1];
                *(float2*)(so + m * 64 + d0)       = make_float2(c0, c1);
                *(float2*)(so + (m + 8) * 64 + d0) = make_float2(c2, c3);
                const float q0 = s_q[d0], q1 = s_q[d0 + 1];
                vr[ai][0] += c0 * q0 + c1 * q1;
                vr[ai][1] += c2 * q0 + c3 * q1;
            }
#pragma unroll
        for (int ai = 0; ai < 4; ai++) {
#pragma unroll
            for (int h = 0; h < 2; h++) {
                vr[ai][h] += __shfl_xor_sync(0xFFFFFFFFu, vr[ai][h], 1);
                vr[ai][h] += __shfl_xor_sync(0xFFFFFFFFu, vr[ai][h], 2);
            }
        }
        if (tig == 0) {
#pragma unroll
            for (int ai = 0; ai < 4; ai++) {
                s_v[wid][ai * 16 + g] = vr[ai][0];
                s_v[wid][ai * 16 + g + 8] = vr[ai][1];
            }
        }
    }
    __syncthreads();
    if (tid < 64)
        outV[bn * 64 + tid] = (s_v[0][tid] + s_v[1][tid]) * s_sinv;
}

// ---------------------------------------------------------------------------
extern "C" void kernel_launch(void* const* d_in, const int* in_sizes, int n_in,
                              void* d_out, int out_size)
{
    const float* query = (const float*)d_in[0];
    const float* key   = (const float*)d_in[1];
    const float* value = (const float*)d_in[2];
    const int*   mask  = (const int*)d_in[3];

    float* out  = (float*)d_out;
    float* outV = out;                        // [B,N,M]
    float* outS = out + V_ELEMS;              // [B,N,M,D]
    float* outZ = out + V_ELEMS + SST_ELEMS;  // [B,N,D]

    rcla_hmma<<<Bq * Nq, 256>>>(query, key, value, mask, outV, outS, outZ);
}

// round 10
// speedup vs baseline: 2.4855x; 1.3960x over previous
#include <cuda_runtime.h>
#include <cstdint>

// Shapes
#define Bq 8
#define Sq 8192
#define Nq 16
#define NCH 2                     // s-chunks (CTAs per bn)
#define SSUB (Sq / NCH)           // 4096
#define ST 32                     // s-rows per tile
#define NT2 (SSUB / ST)           // 128 tiles per CTA
#define RSTRIDE 272               // smem row stride bytes (136 bf16)
#define TILE_B (ST * RSTRIDE)     // 8704
#define BUF_B (2 * TILE_B)        // 17408 = V tile + K tile
#define V_ELEMS 8192
#define SST_ELEMS 524288

// Deterministic reduction scratch
__device__ float g_part[128 * NCH * 4096];   // 4 MB
__device__ float g_zp[128 * NCH * 64];

static __device__ __forceinline__ float elu1(float x) {
    return x > 0.0f ? x + 1.0f : __expf(x);
}
static __device__ __forceinline__ uint32_t smem_u32(const void* p) {
    uint32_t a;
    asm("{ .reg .u64 t; cvta.to.shared.u64 t, %1; cvt.u32.u64 %0, t; }" : "=r"(a) : "l"(p));
    return a;
}
static __device__ __forceinline__ uint32_t pk(float hi, float lo) {
    uint32_t r;
    asm("cvt.rn.bf16x2.f32 %0, %1, %2;" : "=r"(r) : "f"(hi), "f"(lo));
    return r;
}
static __device__ __forceinline__ float bf_lo(uint32_t p) {
    return __uint_as_float(p << 16);
}
static __device__ __forceinline__ float bf_up(uint32_t p) {
    return __uint_as_float(p & 0xFFFF0000u);
}
static __device__ __forceinline__ void ldsm4t(uint32_t* r, uint32_t a) {
    asm volatile("ldmatrix.sync.aligned.m8n8.x4.trans.shared.b16 {%0,%1,%2,%3}, [%4];"
                 : "=r"(r[0]), "=r"(r[1]), "=r"(r[2]), "=r"(r[3]) : "r"(a));
}
static __device__ __forceinline__ void mma16816(float* c, const uint32_t* a,
                                                uint32_t b0, uint32_t b1) {
    asm volatile(
        "mma.sync.aligned.m16n8k16.row.col.f32.bf16.bf16.f32 "
        "{%0,%1,%2,%3}, {%4,%5,%6,%7}, {%8,%9}, {%0,%1,%2,%3};"
        : "+f"(c[0]), "+f"(c[1]), "+f"(c[2]), "+f"(c[3])
        : "r"(a[0]), "r"(a[1]), "r"(a[2]), "r"(a[3]), "r"(b0), "r"(b1));
}
static __device__ __forceinline__ void sts128(uint32_t a, uint32_t x, uint32_t y,
                                              uint32_t z, uint32_t w) {
    asm volatile("st.shared.v4.b32 [%0], {%1,%2,%3,%4};"
                 :: "r"(a), "r"(x), "r"(y), "r"(z), "r"(w) : "memory");
}

// ---------------------------------------------------------------------------
// Phase 1: per (bn, chunk) partial Sst (64x64 fp32) + partial Z.
// ---------------------------------------------------------------------------
__global__ void __launch_bounds__(256, 2) rcla_hmma(
    const float* __restrict__ key,     // [B,S,N,64]
    const float* __restrict__ value,   // [B,S,N,64]
    const int*   __restrict__ kmask)   // [B,S] nonzero = masked
{
    __shared__ __align__(16) unsigned char s_tiles[2 * BUF_B];  // 34816 B
    __shared__ float s_z[ST][64];                               // 8 KB

    const int tid = threadIdx.x;
    const int wid = tid >> 5;
    const int lid = tid & 31;
    const int bn = blockIdx.x;
    const int ch = blockIdx.y;
    const int b = bn >> 4;
    const int n = bn & 15;

    const uint32_t sb = smem_u32(s_tiles);

    // ---- staging mapping ----
    const int s_loc = tid >> 3;            // 0..31
    const int dgrp = (tid & 7) * 8;        // 0..56
    const uint32_t st_off = (uint32_t)s_loc * RSTRIDE + dgrp * 2;

    const int sbase = ch * SSUB + s_loc;
    const float* kg = key   + (((size_t)b * Sq + sbase) * Nq + n) * 64 + dgrp;
    const float* vg = value + (((size_t)b * Sq + sbase) * Nq + n) * 64 + dgrp;
    const int*   mg = kmask + b * Sq + sbase;
    const size_t GSTR = (size_t)ST * Nq * 64;

    // ---- mma mapping ----
    const int mbase = (wid >> 2) * 64;
    const int dbase = (wid & 3) * 32;
    const int g = lid >> 2;
    const int tig = lid & 3;

    const uint32_t offA = (uint32_t)((lid & 7) + ((lid & 16) ? 8 : 0)) * RSTRIDE
                        + (uint32_t)(mbase + ((lid & 8) ? 8 : 0)) * 2;
    const uint32_t offB = (uint32_t)((lid & 7) + ((lid & 8) ? 8 : 0)) * RSTRIDE
                        + (uint32_t)(dbase + ((lid & 16) ? 8 : 0)) * 2;

    float c[4][4][4];
#pragma unroll
    for (int i = 0; i < 4; i++)
#pragma unroll
        for (int j = 0; j < 4; j++)
#pragma unroll
            for (int r = 0; r < 4; r++) c[i][j][r] = 0.0f;
    float zacc[8];
#pragma unroll
    for (int j = 0; j < 8; j++) zacc[j] = 0.0f;

    // prefetch tile 0
    float4 k0 = *(const float4*)kg;
    float4 k1 = *(const float4*)(kg + 4);
    float4 v0 = *(const float4*)vg;
    float4 v1 = *(const float4*)(vg + 4);
    int mk = *mg;

    for (int it = 0; it < NT2; it++) {
        const int buf = it & 1;
        const uint32_t vt = sb + buf * BUF_B;
        const uint32_t kt = vt + TILE_B;

        // ---- stage K (mask + elu + split) ----
        {
            const float mm = mk ? 0.0f : 1.0f;
            float f0 = mm * elu1(k0.x), f1 = mm * elu1(k0.y);
            float f2 = mm * elu1(k0.z), f3 = mm * elu1(k0.w);
            float f4 = mm * elu1(k1.x), f5 = mm * elu1(k1.y);
            float f6 = mm * elu1(k1.z), f7 = mm * elu1(k1.w);
            zacc[0] += f0; zacc[1] += f1; zacc[2] += f2; zacc[3] += f3;
            zacc[4] += f4; zacc[5] += f5; zacc[6] += f6; zacc[7] += f7;
            const uint32_t h01 = pk(f1, f0), h23 = pk(f3, f2);
            const uint32_t h45 = pk(f5, f4), h67 = pk(f7, f6);
            sts128(kt + st_off, h01, h23, h45, h67);
            const uint32_t l01 = pk(f1 - bf_up(h01), f0 - bf_lo(h01));
            const uint32_t l23 = pk(f3 - bf_up(h23), f2 - bf_lo(h23));
            const uint32_t l45 = pk(f5 - bf_up(h45), f4 - bf_lo(h45));
            const uint32_t l67 = pk(f7 - bf_up(h67), f6 - bf_lo(h67));
            sts128(kt + st_off + 128, l01, l23, l45, l67);
        }
        // ---- stage V (split) ----
        {
            const float f0 = v0.x, f1 = v0.y, f2 = v0.z, f3 = v0.w;
            const float f4 = v1.x, f5 = v1.y, f6 = v1.z, f7 = v1.w;
            const uint32_t h01 = pk(f1, f0), h23 = pk(f3, f2);
            const uint32_t h45 = pk(f5, f4), h67 = pk(f7, f6);
            sts128(vt + st_off, h01, h23, h45, h67);
            const uint32_t l01 = pk(f1 - bf_up(h01), f0 - bf_lo(h01));
            const uint32_t l23 = pk(f3 - bf_up(h23), f2 - bf_lo(h23));
            const uint32_t l45 = pk(f5 - bf_up(h45), f4 - bf_lo(h45));
            const uint32_t l67 = pk(f7 - bf_up(h67), f6 - bf_lo(h67));
            sts128(vt + st_off + 128, l01, l23, l45, l67);
        }

        // ---- prefetch next tile ----
        if (it + 1 < NT2) {
            kg += GSTR; vg += GSTR; mg += ST;
            k0 = *(const float4*)kg;
            k1 = *(const float4*)(kg + 4);
            v0 = *(const float4*)vg;
            v1 = *(const float4*)(vg + 4);
            mk = *mg;
        }

        __syncthreads();   // stage visible; also fences reads of this buf @ it-2

        // ---- compute: 2 k-steps of 16 ----
#pragma unroll
        for (int ks = 0; ks < 2; ks++) {
            const uint32_t rowoff = (uint32_t)ks * 16 * RSTRIDE;
            uint32_t a[4][4], bb[2][4];
#pragma unroll
            for (int ai = 0; ai < 4; ai++)
                ldsm4t(a[ai], vt + rowoff + offA + ai * 32);
#pragma unroll
            for (int bj = 0; bj < 2; bj++)
                ldsm4t(bb[bj], kt + rowoff + offB + bj * 32);
#pragma unroll
            for (int ai = 0; ai < 4; ai++)
#pragma unroll
                for (int nb = 0; nb < 4; nb++)
                    mma16816(c[ai][nb], a[ai],
                             bb[nb >> 1][(nb & 1) * 2],
                             bb[nb >> 1][(nb & 1) * 2 + 1]);
        }
        // no trailing sync: next iteration writes the other buffer
    }

    // ---- partial Z ----
#pragma unroll
    for (int j = 0; j < 8; j++) s_z[s_loc][dgrp + j] = zacc[j];
    __syncthreads();
    if (tid < 64) {
        float z = 0.0f;
#pragma unroll
        for (int p = 0; p < ST; p++) z += s_z[p][tid];
        g_zp[(bn * NCH + ch) * 64 + tid] = z;
    }

    // ---- quadrant fold (tiles memory reused as fp32 buffer) ----
    float* fold = (float*)s_tiles;

    if (wid >= 4) {
#pragma unroll
        for (int ai = 0; ai < 4; ai++)
#pragma unroll
            for (int nb = 0; nb < 4; nb++) {
                const int m = ai * 16 + g;
                const int d0 = dbase + nb * 8 + 2 * tig;
                fold[m * 130 + d0]           = c[ai][nb][0];
                fold[m * 130 + d0 + 1]       = c[ai][nb][1];
                fold[(m + 8) * 130 + d0]     = c[ai][nb][2];
                fold[(m + 8) * 130 + d0 + 1] = c[ai][nb][3];
            }
    }
    __syncthreads();
    if (wid < 4) {
#pragma unroll
        for (int ai = 0; ai < 4; ai++)
#pragma unroll
            for (int nb = 0; nb < 4; nb++) {
                const int m = ai * 16 + g;
                const int d0 = dbase + nb * 8 + 2 * tig;
                c[ai][nb][0] += fold[m * 130 + d0];
                c[ai][nb][1] += fold[m * 130 + d0 + 1];
                c[ai][nb][2] += fold[(m + 8) * 130 + d0];
                c[ai][nb][3] += fold[(m + 8) * 130 + d0 + 1];
            }
    }
    __syncthreads();
    if (wid == 2 || wid == 3) {
#pragma unroll
        for (int ai = 0; ai < 4; ai++)
#pragma unroll
            for (int nb = 0; nb < 4; nb++) {
                const int m = ai * 16 + g;
                const int d0 = dbase - 64 + nb * 8 + 2 * tig;
                fold[m * 66 + d0]           = c[ai][nb][0];
                fold[m * 66 + d0 + 1]       = c[ai][nb][1];
                fold[(m + 8) * 66 + d0]     = c[ai][nb][2];
                fold[(m + 8) * 66 + d0 + 1] = c[ai][nb][3];
            }
    }
    __syncthreads();

    // ---- warps 0,1: write partial Sst ----
    if (wid < 2) {
        float* so = g_part + ((size_t)bn * NCH + ch) * 4096;
#pragma unroll
        for (int ai = 0; ai < 4; ai++)
#pragma unroll
            for (int nb = 0; nb < 4; nb++) {
                const int m = ai * 16 + g;
                const int d0 = dbase + nb * 8 + 2 * tig;
                float c0 = c[ai][nb][0] + fold[m * 66 + d0];
                float c1 = c[ai][nb][1] + fold[m * 66 + d0 + 1];
                float c2 = c[ai][nb][2] + fold[(m + 8) * 66 + d0];
                float c3 = c[ai][nb][3] + fold[(m + 8) * 66 + d0 + 1];
                *(float2*)(so + m * 64 + d0)       = make_float2(c0, c1);
                *(float2*)(so + (m + 8) * 64 + d0) = make_float2(c2, c3);
            }
    }
}

// ---------------------------------------------------------------------------
// Phase 2: deterministic 2-way reduction + epilogue. One block per bn.
// ---------------------------------------------------------------------------
__global__ void __launch_bounds__(256) rcla_reduce(
    const float* __restrict__ query,  // [B,N,64]
    float* __restrict__ outV,         // [B,N,64]
    float* __restrict__ outS,         // [B,N,64,64]
    float* __restrict__ outZ)         // [B,N,64]
{
    const int bn = blockIdx.x;
    const int tid = threadIdx.x;

    __shared__ float sst[4096];
    __shared__ float qs[64];
    __shared__ float red[64];
    __shared__ float sinv;

    const float* p0 = g_part + (size_t)bn * NCH * 4096;
    for (int e = tid; e < 4096; e += 256) {
        float s = p0[e] + p0[4096 + e];
        sst[e] = s;
        outS[(size_t)bn * 4096 + e] = s;
    }
    if (tid < 64) {
        const float z = g_zp[bn * NCH * 64 + tid] + g_zp[(bn * NCH + 1) * 64 + tid];
        outZ[bn * 64 + tid] = z;
        const float q = elu1(query[bn * 64 + tid]);
        qs[tid] = q;
        red[tid] = q * z;
    }
    __syncthreads();
    if (tid == 0) {
        float s = 0.0f;
#pragma unroll
        for (int d = 0; d < 64; d++) s += red[d];
        sinv = 1.0f / (s + 1e-6f);
    }
    __syncthreads();
    if (tid < 64) {
        float v = 0.0f;
#pragma unroll
        for (int d = 0; d < 64; d++) v += qs[d] * sst[tid * 64 + d];
        outV[bn * 64 + tid] = v * sinv;
    }
}

// ---------------------------------------------------------------------------
extern "C" void kernel_launch(void* const* d_in, const int* in_sizes, int n_in,
                              void* d_out, int out_size)
{
    const float* query = (const float*)d_in[0];
    const float* key   = (const float*)d_in[1];
    const float* value = (const float*)d_in[2];
    const int*   mask  = (const int*)d_in[3];

    float* out  = (float*)d_out;
    float* outV = out;                        // [B,N,M]
    float* outS = out + V_ELEMS;              // [B,N,M,D]
    float* outZ = out + V_ELEMS + SST_ELEMS;  // [B,N,D]

    rcla_hmma<<<dim3(128, NCH), 256>>>(key, value, mask);
    rcla_reduce<<<128, 256>>>(query, outV, outS, outZ);
}